// round 3
// baseline (speedup 1.0000x reference)
#include <cuda_runtime.h>
#include <cuda_bf16.h>
#include <cstdint>

// ---------------------------------------------------------------------------
// Problem constants
// ---------------------------------------------------------------------------
#define VOCAB 10000
#define VPAD  10240          // 40 * 256
#define EMB   64
#define HID   128
#define BATCH 32
#define TLEN  256
#define ROWS  (BATCH * TLEN) // 8192

// ---------------------------------------------------------------------------
// Device scratch (no allocation allowed)
// ---------------------------------------------------------------------------
__device__ __align__(16) float          g_xw[ROWS * HID];       // 4 MB
__device__ __align__(16) __nv_bfloat16  g_rnn_hi[ROWS * HID];   // 2 MB
__device__ __align__(16) __nv_bfloat16  g_rnn_lo[ROWS * HID];   // 2 MB
__device__ __align__(16) __nv_bfloat16  g_wdt_hi[VPAD * HID];   // 2.6 MB
__device__ __align__(16) __nv_bfloat16  g_wdt_lo[VPAD * HID];   // 2.6 MB
__device__ int g_ids_is64;

// ---------------------------------------------------------------------------
// MMA / ldmatrix helpers (plain-target sm_80+ instructions; no tcgen05)
// ---------------------------------------------------------------------------
__device__ __forceinline__ uint32_t smem_u32(const void* p) {
    uint32_t a;
    asm("{ .reg .u64 t; cvta.to.shared.u64 t, %1; cvt.u32.u64 %0, t; }" : "=r"(a) : "l"(p));
    return a;
}

__device__ __forceinline__ void ldsm_x4(uint32_t* r, uint32_t addr) {
    asm volatile("ldmatrix.sync.aligned.m8n8.x4.shared.b16 {%0,%1,%2,%3}, [%4];"
                 : "=r"(r[0]), "=r"(r[1]), "=r"(r[2]), "=r"(r[3]) : "r"(addr));
}

__device__ __forceinline__ void mma16816(float* c, const uint32_t* a,
                                         uint32_t b0, uint32_t b1) {
    asm volatile("mma.sync.aligned.m16n8k16.row.col.f32.bf16.bf16.f32 "
                 "{%0,%1,%2,%3}, {%4,%5,%6,%7}, {%8,%9}, {%0,%1,%2,%3};"
                 : "+f"(c[0]), "+f"(c[1]), "+f"(c[2]), "+f"(c[3])
                 : "r"(a[0]), "r"(a[1]), "r"(a[2]), "r"(a[3]), "r"(b0), "r"(b1));
}

// ---------------------------------------------------------------------------
// Kernel 0: detect inp_ids dtype. If int64 (values < 2^31), every odd 32-bit
// word is zero. Sample 2048 odd words; random int32 ids make this ~impossible.
// ---------------------------------------------------------------------------
__global__ void k_detect(const unsigned int* __restrict__ w) {
    __shared__ int any;
    if (threadIdx.x == 0) any = 0;
    __syncthreads();
    unsigned int x = 0;
    for (int i = threadIdx.x; i < 2048; i += 256) x |= w[2 * i + 1];
    if (x) atomicOr(&any, 1);
    __syncthreads();
    if (threadIdx.x == 0) g_ids_is64 = any ? 0 : 1;
}

// ---------------------------------------------------------------------------
// Kernel 1: transpose + bf16-split Wd -> WdT[v][k] (hi/lo), zero-padded to VPAD
// ---------------------------------------------------------------------------
__global__ void k_wdt(const float* __restrict__ Wd) {
    __shared__ float tile[32][33];
    int n0 = blockIdx.x * 32;   // vocab
    int k0 = blockIdx.y * 32;   // hid
    int tx = threadIdx.x, ty = threadIdx.y;  // 32 x 8
    #pragma unroll
    for (int i = 0; i < 32; i += 8) {
        int k = k0 + ty + i, n = n0 + tx;
        tile[ty + i][tx] = (n < VOCAB) ? Wd[(size_t)k * VOCAB + n] : 0.f;
    }
    __syncthreads();
    #pragma unroll
    for (int i = 0; i < 32; i += 8) {
        int n = n0 + ty + i, k = k0 + tx;
        float v = tile[tx][ty + i];
        __nv_bfloat16 hi = __float2bfloat16(v);
        g_wdt_hi[n * HID + k] = hi;
        g_wdt_lo[n * HID + k] = __float2bfloat16(v - __bfloat162float(hi));
    }
}

// ---------------------------------------------------------------------------
// Kernel 2: embedding lookup + input projection: xw[r][j] = emb[ids[r]] @ W + b
// ---------------------------------------------------------------------------
__global__ void k_embed(const void* __restrict__ ids_raw,
                        const float* __restrict__ emb,
                        const float* __restrict__ W,
                        const float* __restrict__ b) {
    __shared__ float Ws[EMB * HID];   // 32 KB
    __shared__ float xs[16][EMB];     // 4 KB
    int j = threadIdx.x;  // 0..127
    int is64 = g_ids_is64;
    for (int i = j; i < EMB * HID; i += 128) Ws[i] = W[i];
    int r0 = blockIdx.x * 16;
    for (int p = j; p < 16 * EMB; p += 128) {
        int ri = p >> 6, e = p & 63;
        long long id = is64 ? ((const long long*)ids_raw)[r0 + ri]
                            : (long long)((const int*)ids_raw)[r0 + ri];
        xs[ri][e] = emb[id * EMB + e];
    }
    __syncthreads();
    float bj = b[j];
    #pragma unroll 1
    for (int ri = 0; ri < 16; ri++) {
        float a0 = bj, a1 = 0.f;
        #pragma unroll
        for (int e = 0; e < EMB; e += 2) {
            a0 += xs[ri][e]     * Ws[e * HID + j];
            a1 += xs[ri][e + 1] * Ws[(e + 1) * HID + j];
        }
        g_xw[(r0 + ri) * HID + j] = a0 + a1;
    }
}

// ---------------------------------------------------------------------------
// Kernel 3: RNN scan. One CTA per batch (32 CTAs). Thread j owns hid unit j;
// U column j lives in 128 registers. h ping-pongs in SMEM (1 barrier / step).
// Emits the bf16 hi/lo split of h directly for the output GEMM.
// ---------------------------------------------------------------------------
__global__ void __launch_bounds__(HID, 1) k_scan(const float* __restrict__ U) {
    __shared__ float4 h4[2][HID / 4];
    int bb = blockIdx.x;
    int j  = threadIdx.x;

    float u[HID];
    #pragma unroll
    for (int i = 0; i < HID; i++) u[i] = U[i * HID + j];

    if (j < HID / 4) h4[0][j] = make_float4(0.f, 0.f, 0.f, 0.f);
    __syncthreads();

    const float* xwp = g_xw + (size_t)bb * TLEN * HID + j;
    float xw_cur = xwp[0];
    int buf = 0;

    #pragma unroll 1
    for (int t = 0; t < TLEN; t++) {
        float xw_next = (t < TLEN - 1) ? xwp[(t + 1) * HID] : 0.f;
        float a0 = xw_cur, a1 = 0.f, a2 = 0.f, a3 = 0.f;
        #pragma unroll
        for (int q = 0; q < HID / 4; q++) {
            float4 hv = h4[buf][q];
            a0 += hv.x * u[4 * q + 0];
            a1 += hv.y * u[4 * q + 1];
            a2 += hv.z * u[4 * q + 2];
            a3 += hv.w * u[4 * q + 3];
        }
        float z = (a0 + a1) + (a2 + a3);
        float e = expf(2.f * z);
        float h = 1.f - 2.f / (e + 1.f);

        __nv_bfloat16 hi = __float2bfloat16(h);
        float lo = h - __bfloat162float(hi);
        int idx = (bb * TLEN + t) * HID + j;
        g_rnn_hi[idx] = hi;
        g_rnn_lo[idx] = __float2bfloat16(lo);

        ((float*)&h4[buf ^ 1][0])[j] = h;
        __syncthreads();
        buf ^= 1;
        xw_cur = xw_next;
    }
}

// ---------------------------------------------------------------------------
// Kernel 4: output GEMM via mma.sync (HMMA), split-bf16 3-product scheme.
//   out[bt][v] = rnn[bt][k] @ WdT[v][k]^T + bd[v]
// CTA tile: 128 bt x 256 v, K=128 resident. 8 warps, warp tile 64x64.
// SMEM: A (rnn hi/lo) 64 KB + B (wdt hi/lo) 128 KB = 192 KB, 1 CTA/SM.
// XOR swizzle (chunk ^= row&7 on 16B chunks) -> conflict-free ldmatrix.
// ---------------------------------------------------------------------------
#define SA_BYTES  (2 * 128 * 256)   // 65536
#define SB_BYTES  (2 * 256 * 256)   // 131072
#define SM_TOTAL  (SA_BYTES + SB_BYTES)

__global__ void __launch_bounds__(256, 1) k_gemm(const float* __restrict__ bd,
                                                 float* __restrict__ out) {
    extern __shared__ char smem[];
    uint32_t sA = smem_u32(smem);
    uint32_t sB = sA + SA_BYTES;

    int tid  = threadIdx.x;
    int wid  = tid >> 5;
    int lane = tid & 31;
    int v0   = blockIdx.x * 256;
    int bt0  = blockIdx.y * 128;

    // ---- load A tile: 2 splits x 128 rows x 16 chunks of 16B ----
    #pragma unroll
    for (int i = tid; i < 4096; i += 256) {
        int split = i >> 11, row = (i >> 4) & 127, ch = i & 15;
        const __nv_bfloat16* src = split ? g_rnn_lo : g_rnn_hi;
        uint4 v = *(const uint4*)(src + (size_t)(bt0 + row) * HID + ch * 8);
        uint32_t dst = sA + split * 32768 + row * 256 + ((ch ^ (row & 7)) << 4);
        asm volatile("st.shared.v4.b32 [%0], {%1,%2,%3,%4};"
                     :: "r"(dst), "r"(v.x), "r"(v.y), "r"(v.z), "r"(v.w));
    }
    // ---- load B tile: 2 splits x 256 rows x 16 chunks ----
    #pragma unroll
    for (int i = tid; i < 8192; i += 256) {
        int split = i >> 12, row = (i >> 4) & 255, ch = i & 15;
        const __nv_bfloat16* src = split ? g_wdt_lo : g_wdt_hi;
        uint4 v = *(const uint4*)(src + (size_t)(v0 + row) * HID + ch * 8);
        uint32_t dst = sB + split * 65536 + row * 256 + ((ch ^ (row & 7)) << 4);
        asm volatile("st.shared.v4.b32 [%0], {%1,%2,%3,%4};"
                     :: "r"(dst), "r"(v.x), "r"(v.y), "r"(v.z), "r"(v.w));
    }
    __syncthreads();

    int wm = wid & 1;          // 2 warps over M (64 each)
    int wn = wid >> 1;         // 4 warps over N (64 each)

    // per-lane ldmatrix row components
    int rA = ((lane >> 3) & 1) * 8 + (lane & 7);  // row within m16 block
    int kcA = lane >> 4;                          // k-chunk half (0/1)
    int rB = ((lane >> 4) & 1) * 8 + (lane & 7);  // row within n16 block
    int kcB = (lane >> 3) & 1;
    int lx = lane & 7;                            // swizzle xor

    float c[4][8][4];
    #pragma unroll
    for (int mb = 0; mb < 4; mb++)
        #pragma unroll
        for (int nb = 0; nb < 8; nb++)
            #pragma unroll
            for (int q = 0; q < 4; q++) c[mb][nb][q] = 0.f;

    // combos: (A_hi,B_hi), (A_lo,B_hi), (A_hi,B_lo)
    #pragma unroll 1
    for (int cmb = 0; cmb < 3; cmb++) {
        uint32_t aBase = sA + (cmb == 1 ? 32768 : 0)
                       + (uint32_t)(wm * 64 + rA) * 256;
        uint32_t bBase = sB + (cmb == 2 ? 65536 : 0)
                       + (uint32_t)(wn * 64 + rB) * 256;
        #pragma unroll 1
        for (int ks = 0; ks < 8; ks++) {
            uint32_t a[4][4], b[4][4];
            int kA = (ks * 2 + kcA) ^ lx;
            int kB = (ks * 2 + kcB) ^ lx;
            #pragma unroll
            for (int mb = 0; mb < 4; mb++)
                ldsm_x4(a[mb], aBase + (uint32_t)(mb * 16) * 256 + (kA << 4));
            #pragma unroll
            for (int nb = 0; nb < 4; nb++)
                ldsm_x4(b[nb], bBase + (uint32_t)(nb * 16) * 256 + (kB << 4));
            #pragma unroll
            for (int mb = 0; mb < 4; mb++)
                #pragma unroll
                for (int nbi = 0; nbi < 8; nbi++)
                    mma16816(c[mb][nbi], a[mb],
                             b[nbi >> 1][(nbi & 1) * 2],
                             b[nbi >> 1][(nbi & 1) * 2 + 1]);
        }
    }

    // ---- epilogue: bias + store, out[bt][v], 32B-sector-aligned quads ----
    #pragma unroll
    for (int nbi = 0; nbi < 8; nbi++) {
        int col = v0 + wn * 64 + nbi * 8 + (lane & 3) * 2;
        if (col < VOCAB) {
            float b0 = bd[col], b1 = bd[col + 1];
            #pragma unroll
            for (int mb = 0; mb < 4; mb++) {
                int r = bt0 + wm * 64 + mb * 16 + (lane >> 2);
                float2 lo = make_float2(c[mb][nbi][0] + b0, c[mb][nbi][1] + b1);
                float2 hi = make_float2(c[mb][nbi][2] + b0, c[mb][nbi][3] + b1);
                *(float2*)(out + (size_t)r * VOCAB + col) = lo;
                *(float2*)(out + (size_t)(r + 8) * VOCAB + col) = hi;
            }
        }
    }
}

// ---------------------------------------------------------------------------
// Launch
// ---------------------------------------------------------------------------
extern "C" void kernel_launch(void* const* d_in, const int* in_sizes, int n_in,
                              void* d_out, int out_size) {
    const void*  ids = d_in[0];
    const float* emb = (const float*)d_in[1];
    const float* W   = (const float*)d_in[2];
    const float* U   = (const float*)d_in[3];
    const float* b   = (const float*)d_in[4];
    const float* Wd  = (const float*)d_in[5];
    const float* bd  = (const float*)d_in[6];
    float* out = (float*)d_out;

    cudaFuncSetAttribute(k_gemm, cudaFuncAttributeMaxDynamicSharedMemorySize, SM_TOTAL);

    k_detect<<<1, 256>>>((const unsigned int*)ids);
    k_wdt<<<dim3(VPAD / 32, HID / 32), dim3(32, 8)>>>(Wd);
    k_embed<<<ROWS / 16, 128>>>(ids, emb, W, b);
    k_scan<<<BATCH, HID>>>(U);
    k_gemm<<<dim3(VPAD / 256, ROWS / 128), 256, SM_TOTAL>>>(bd, out);
}

// round 4
// speedup vs baseline: 1.2632x; 1.2632x over previous
#include <cuda_runtime.h>
#include <cuda_fp16.h>
#include <cuda_bf16.h>
#include <cstdint>

// ---------------------------------------------------------------------------
// Problem constants
// ---------------------------------------------------------------------------
#define VOCAB 10000
#define VPAD  10240          // 40 * 256
#define EMB   64
#define HID   128
#define BATCH 32
#define TLEN  256
#define ROWS  (BATCH * TLEN) // 8192

// ---------------------------------------------------------------------------
// Device scratch (no allocation allowed)
// ---------------------------------------------------------------------------
__device__ __align__(16) float   g_xw[ROWS * HID];       // 4 MB
__device__ __align__(16) __half  g_rnn_hi[ROWS * HID];   // 2 MB
__device__ __align__(16) __half  g_rnn_lo[ROWS * HID];   // 2 MB
__device__ __align__(16) __half  g_wdt_h[VPAD * HID];    // 2.6 MB (hi only)
__device__ int g_ids_is64;

// ---------------------------------------------------------------------------
// PTX helpers (plain-target instructions only; no tcgen05)
// ---------------------------------------------------------------------------
__device__ __forceinline__ uint32_t smem_u32(const void* p) {
    uint32_t a;
    asm("{ .reg .u64 t; cvta.to.shared.u64 t, %1; cvt.u32.u64 %0, t; }" : "=r"(a) : "l"(p));
    return a;
}
__device__ __forceinline__ void ldsm_x4(uint32_t* r, uint32_t addr) {
    asm volatile("ldmatrix.sync.aligned.m8n8.x4.shared.b16 {%0,%1,%2,%3}, [%4];"
                 : "=r"(r[0]), "=r"(r[1]), "=r"(r[2]), "=r"(r[3]) : "r"(addr));
}
__device__ __forceinline__ void mma16816(float* c, const uint32_t* a,
                                         uint32_t b0, uint32_t b1) {
    asm volatile("mma.sync.aligned.m16n8k16.row.col.f32.f16.f16.f32 "
                 "{%0,%1,%2,%3}, {%4,%5,%6,%7}, {%8,%9}, {%0,%1,%2,%3};"
                 : "+f"(c[0]), "+f"(c[1]), "+f"(c[2]), "+f"(c[3])
                 : "r"(a[0]), "r"(a[1]), "r"(a[2]), "r"(a[3]), "r"(b0), "r"(b1));
}
__device__ __forceinline__ void cp16(uint32_t dst, const void* src) {
    asm volatile("cp.async.cg.shared.global [%0], [%1], 16;" :: "r"(dst), "l"(src));
}
#define CP_COMMIT()  asm volatile("cp.async.commit_group;" ::: "memory")
#define CP_WAIT(N)   asm volatile("cp.async.wait_group %0;" :: "n"(N) : "memory")

// packed f32x2 fma (Blackwell base; ptxas encodes FFMA2 only via this PTX)
__device__ __forceinline__ void fma2(unsigned long long& acc,
                                     unsigned long long a, unsigned long long b) {
    asm("fma.rn.f32x2 %0, %1, %2, %0;" : "+l"(acc) : "l"(a), "l"(b));
}
__device__ __forceinline__ unsigned long long pack2(float x, float y) {
    unsigned long long p;
    asm("mov.b64 %0, {%1, %2};" : "=l"(p) : "f"(x), "f"(y));
    return p;
}
__device__ __forceinline__ void unpack2(unsigned long long p, float& x, float& y) {
    asm("mov.b64 {%0, %1}, %2;" : "=f"(x), "=f"(y) : "l"(p));
}

// ---------------------------------------------------------------------------
// Kernel 0: detect inp_ids dtype (int64 vs int32) via odd 32-bit words
// ---------------------------------------------------------------------------
__global__ void k_detect(const unsigned int* __restrict__ w) {
    __shared__ int any;
    if (threadIdx.x == 0) any = 0;
    __syncthreads();
    unsigned int x = 0;
    for (int i = threadIdx.x; i < 2048; i += 256) x |= w[2 * i + 1];
    if (x) atomicOr(&any, 1);
    __syncthreads();
    if (threadIdx.x == 0) g_ids_is64 = any ? 0 : 1;
}

// ---------------------------------------------------------------------------
// Kernel 1: transpose Wd -> WdT[v][k] fp16, zero-padded to VPAD
// ---------------------------------------------------------------------------
__global__ void k_wdt(const float* __restrict__ Wd) {
    __shared__ float tile[32][33];
    int n0 = blockIdx.x * 32;   // vocab
    int k0 = blockIdx.y * 32;   // hid
    int tx = threadIdx.x, ty = threadIdx.y;  // 32 x 8
    #pragma unroll
    for (int i = 0; i < 32; i += 8) {
        int k = k0 + ty + i, n = n0 + tx;
        tile[ty + i][tx] = (n < VOCAB) ? Wd[(size_t)k * VOCAB + n] : 0.f;
    }
    __syncthreads();
    #pragma unroll
    for (int i = 0; i < 32; i += 8) {
        int n = n0 + ty + i, k = k0 + tx;
        g_wdt_h[n * HID + k] = __float2half(tile[tx][ty + i]);
    }
}

// ---------------------------------------------------------------------------
// Kernel 2: embedding lookup + input projection
// ---------------------------------------------------------------------------
__global__ void k_embed(const void* __restrict__ ids_raw,
                        const float* __restrict__ emb,
                        const float* __restrict__ W,
                        const float* __restrict__ b) {
    __shared__ float Ws[EMB * HID];
    __shared__ float xs[16][EMB];
    int j = threadIdx.x;
    int is64 = g_ids_is64;
    for (int i = j; i < EMB * HID; i += 128) Ws[i] = W[i];
    int r0 = blockIdx.x * 16;
    for (int p = j; p < 16 * EMB; p += 128) {
        int ri = p >> 6, e = p & 63;
        long long id = is64 ? ((const long long*)ids_raw)[r0 + ri]
                            : (long long)((const int*)ids_raw)[r0 + ri];
        xs[ri][e] = emb[id * EMB + e];
    }
    __syncthreads();
    float bj = b[j];
    #pragma unroll 1
    for (int ri = 0; ri < 16; ri++) {
        float a0 = bj, a1 = 0.f;
        #pragma unroll
        for (int e = 0; e < EMB; e += 2) {
            a0 += xs[ri][e]     * Ws[e * HID + j];
            a1 += xs[ri][e + 1] * Ws[(e + 1) * HID + j];
        }
        g_xw[(r0 + ri) * HID + j] = a0 + a1;
    }
}

// ---------------------------------------------------------------------------
// Kernel 3: RNN scan, f32x2 packed FMAs. One CTA per batch; thread j owns
// unit j; U column packed in 128 regs as 64 f32x2 pairs; h in SMEM.
// ---------------------------------------------------------------------------
__global__ void __launch_bounds__(HID, 1) k_scan(const float* __restrict__ U) {
    __shared__ __align__(16) float h[2][HID];
    int bb = blockIdx.x;
    int j  = threadIdx.x;

    unsigned long long u2[HID / 2];
    #pragma unroll
    for (int q = 0; q < HID / 2; q++)
        u2[q] = pack2(U[(2 * q) * HID + j], U[(2 * q + 1) * HID + j]);

    h[0][j] = 0.f;
    __syncthreads();

    const float* xwp = g_xw + (size_t)bb * TLEN * HID + j;
    float xw_cur = xwp[0];
    int buf = 0;

    #pragma unroll 1
    for (int t = 0; t < TLEN; t++) {
        float xw_next = (t < TLEN - 1) ? xwp[(t + 1) * HID] : 0.f;

        unsigned long long a0 = pack2(xw_cur, 0.f), a1 = 0ull, a2 = 0ull, a3 = 0ull;
        const ulonglong2* hp = (const ulonglong2*)&h[buf][0];
        #pragma unroll
        for (int i = 0; i < 32; i += 2) {
            ulonglong2 ha = hp[i];
            ulonglong2 hb = hp[i + 1];
            fma2(a0, u2[2 * i],     ha.x);
            fma2(a1, u2[2 * i + 1], ha.y);
            fma2(a2, u2[2 * i + 2], hb.x);
            fma2(a3, u2[2 * i + 3], hb.y);
        }
        float s0, s1, s2, s3, s4, s5, s6, s7;
        unpack2(a0, s0, s1); unpack2(a1, s2, s3);
        unpack2(a2, s4, s5); unpack2(a3, s6, s7);
        float z = ((s0 + s1) + (s2 + s3)) + ((s4 + s5) + (s6 + s7));

        float e = __expf(2.f * z);
        float hval = 1.f - __fdividef(2.f, e + 1.f);

        __half hi = __float2half(hval);
        float lo = hval - __half2float(hi);
        int idx = (bb * TLEN + t) * HID + j;
        g_rnn_hi[idx] = hi;
        g_rnn_lo[idx] = __float2half(lo);

        h[buf ^ 1][j] = hval;
        __syncthreads();
        buf ^= 1;
        xw_cur = xw_next;
    }
}

// ---------------------------------------------------------------------------
// Kernel 4: output GEMM, fp16 2-product (A=rnn hi/lo split, B=wdt fp16).
//   out[bt][v] = rnn[bt][k] @ WdT[v][k]^T + bd[v]
// CTA: v-tile 256 resident B (64 KB), 2 bt-tiles of 128, A double-buffered
// via cp.async (2 x 64 KB). 8 warps, warp tile 64x64.
// ---------------------------------------------------------------------------
#define SB_BYTES   65536                 // 256 x 256B (fp16 hi only)
#define SA_BYTES   65536                 // per buffer: hi 32K + lo 32K
#define SM_TOTAL   (SB_BYTES + 2 * SA_BYTES)   // 192 KB

__global__ void __launch_bounds__(256, 1) k_gemm(const float* __restrict__ bd,
                                                 float* __restrict__ out) {
    extern __shared__ char smem[];
    uint32_t sB = smem_u32(smem);
    uint32_t sA0 = sB + SB_BYTES;

    int tid  = threadIdx.x;
    int wid  = tid >> 5;
    int lane = tid & 31;
    int v0   = blockIdx.x * 256;
    int btg  = blockIdx.y * 256;        // 2 tiles of 128

    // ---- prologue: async-load B (resident) + A tile 0, then A tile 1 ----
    #pragma unroll
    for (int i = tid; i < 4096; i += 256) {       // B: 256 rows x 16 chunks
        int row = i >> 4, ch = i & 15;
        uint32_t dst = sB + row * 256 + ((ch ^ (row & 7)) << 4);
        cp16(dst, g_wdt_h + (size_t)(v0 + row) * HID + ch * 8);
    }
    #pragma unroll
    for (int i = tid; i < 4096; i += 256) {       // A0: hi/lo x 128 rows x 16
        int split = i >> 11, row = (i >> 4) & 127, ch = i & 15;
        const __half* src = split ? g_rnn_lo : g_rnn_hi;
        uint32_t dst = sA0 + split * 32768 + row * 256 + ((ch ^ (row & 7)) << 4);
        cp16(dst, src + (size_t)(btg + row) * HID + ch * 8);
    }
    CP_COMMIT();                                   // G0 = B + A0
    #pragma unroll
    for (int i = tid; i < 4096; i += 256) {       // A1
        int split = i >> 11, row = (i >> 4) & 127, ch = i & 15;
        const __half* src = split ? g_rnn_lo : g_rnn_hi;
        uint32_t dst = sA0 + SA_BYTES + split * 32768 + row * 256 + ((ch ^ (row & 7)) << 4);
        cp16(dst, src + (size_t)(btg + 128 + row) * HID + ch * 8);
    }
    CP_COMMIT();                                   // G1 = A1

    int wm = wid & 1;          // 2 warps over bt (64 each)
    int wn = wid >> 1;         // 4 warps over v  (64 each)
    int rA  = ((lane >> 3) & 1) * 8 + (lane & 7);
    int kcA = lane >> 4;
    int rB  = ((lane >> 4) & 1) * 8 + (lane & 7);
    int kcB = (lane >> 3) & 1;
    int lx  = lane & 7;

    #pragma unroll 1
    for (int it = 0; it < 2; it++) {
        if (it == 0) { CP_WAIT(1); } else { CP_WAIT(0); }
        __syncthreads();

        uint32_t sAb = sA0 + it * SA_BYTES;
        int bt0 = btg + it * 128;

        float c[4][8][4];
        #pragma unroll
        for (int mb = 0; mb < 4; mb++)
            #pragma unroll
            for (int nb = 0; nb < 8; nb++)
                #pragma unroll
                for (int q = 0; q < 4; q++) c[mb][nb][q] = 0.f;

        #pragma unroll 1
        for (int cmb = 0; cmb < 2; cmb++) {        // A_hi * B, A_lo * B
            uint32_t aBase = sAb + cmb * 32768 + (uint32_t)(wm * 64 + rA) * 256;
            uint32_t bBase = sB + (uint32_t)(wn * 64 + rB) * 256;
            #pragma unroll 1
            for (int ks = 0; ks < 8; ks++) {
                uint32_t a[4][4], b[4][4];
                int kA = (ks * 2 + kcA) ^ lx;
                int kB = (ks * 2 + kcB) ^ lx;
                #pragma unroll
                for (int mb = 0; mb < 4; mb++)
                    ldsm_x4(a[mb], aBase + (uint32_t)(mb * 16) * 256 + (kA << 4));
                #pragma unroll
                for (int nb = 0; nb < 4; nb++)
                    ldsm_x4(b[nb], bBase + (uint32_t)(nb * 16) * 256 + (kB << 4));
                #pragma unroll
                for (int mb = 0; mb < 4; mb++)
                    #pragma unroll
                    for (int nbi = 0; nbi < 8; nbi++)
                        mma16816(c[mb][nbi], a[mb],
                                 b[nbi >> 1][(nbi & 1) * 2],
                                 b[nbi >> 1][(nbi & 1) * 2 + 1]);
            }
        }

        // ---- epilogue: bias + store ----
        #pragma unroll
        for (int nbi = 0; nbi < 8; nbi++) {
            int col = v0 + wn * 64 + nbi * 8 + (lane & 3) * 2;
            if (col < VOCAB) {
                float b0 = bd[col], b1 = bd[col + 1];
                #pragma unroll
                for (int mb = 0; mb < 4; mb++) {
                    int r = bt0 + wm * 64 + mb * 16 + (lane >> 2);
                    float2 lo = make_float2(c[mb][nbi][0] + b0, c[mb][nbi][1] + b1);
                    float2 hi = make_float2(c[mb][nbi][2] + b0, c[mb][nbi][3] + b1);
                    *(float2*)(out + (size_t)r * VOCAB + col) = lo;
                    *(float2*)(out + (size_t)(r + 8) * VOCAB + col) = hi;
                }
            }
        }
        __syncthreads();
    }
}

// ---------------------------------------------------------------------------
// Launch: fork k_wdt onto a side stream (captured via events), join for gemm
// ---------------------------------------------------------------------------
extern "C" void kernel_launch(void* const* d_in, const int* in_sizes, int n_in,
                              void* d_out, int out_size) {
    const void*  ids = d_in[0];
    const float* emb = (const float*)d_in[1];
    const float* W   = (const float*)d_in[2];
    const float* U   = (const float*)d_in[3];
    const float* b   = (const float*)d_in[4];
    const float* Wd  = (const float*)d_in[5];
    const float* bd  = (const float*)d_in[6];
    float* out = (float*)d_out;

    static cudaStream_t s2 = nullptr;
    static cudaEvent_t eFork = nullptr, eJoin = nullptr;
    if (!s2) {
        cudaStreamCreateWithFlags(&s2, cudaStreamNonBlocking);
        cudaEventCreateWithFlags(&eFork, cudaEventDisableTiming);
        cudaEventCreateWithFlags(&eJoin, cudaEventDisableTiming);
        cudaFuncSetAttribute(k_gemm, cudaFuncAttributeMaxDynamicSharedMemorySize, SM_TOTAL);
    }

    cudaEventRecord(eFork, 0);
    cudaStreamWaitEvent(s2, eFork, 0);
    k_wdt<<<dim3(VPAD / 32, HID / 32), dim3(32, 8), 0, s2>>>(Wd);
    cudaEventRecord(eJoin, s2);

    k_detect<<<1, 256>>>((const unsigned int*)ids);
    k_embed<<<ROWS / 16, 128>>>(ids, emb, W, b);
    k_scan<<<BATCH, HID>>>(U);

    cudaStreamWaitEvent(0, eJoin, 0);
    k_gemm<<<dim3(VPAD / 256, ROWS / 256), 256, SM_TOTAL>>>(bd, out);
}